// round 1
// baseline (speedup 1.0000x reference)
#include <cuda_runtime.h>
#include <cstdint>
#include <cstddef>

#define B_     128
#define C_     3
#define IMG_   224
#define P_     16
#define HP_    14
#define NP_    196
#define S_     197
#define D_     384
#define HEADS_ 6
#define HD_    64
#define DEPTH_ 12
#define HID_   1536
#define NCLS_  100
#define PD_    768
#define T_     (B_*S_)    // 25216
#define BT_    (B_*NP_)   // 25088
#define TRID_  (3*D_)     // 1152

// ---------------- scratch (static device globals; no allocation) ----------------
__device__ float g_patches[(size_t)BT_*PD_];   // 77 MB
__device__ float g_tok[(size_t)BT_*D_];        // 38.5 MB
__device__ float g_h[(size_t)T_*D_];
__device__ float g_xn[(size_t)T_*D_];
__device__ float g_qkv[(size_t)T_*TRID_];      // 116 MB
__device__ float g_ctx[(size_t)T_*D_];
__device__ float g_hid[(size_t)T_*HID_];       // 155 MB
__device__ float g_cls[B_*D_];

// ---------------- patchify ----------------
__global__ void patchify_k(const float* __restrict__ x, float* __restrict__ out) {
    int idx = blockIdx.x * blockDim.x + threadIdx.x;
    if (idx >= BT_*PD_) return;
    int t = idx / PD_, j = idx - t*PD_;
    int b = t / NP_, p = t - b*NP_;
    int ph = p / HP_, pw = p - ph*HP_;
    int c = j >> 8, r = (j >> 4) & 15, col = j & 15;
    out[idx] = x[(((size_t)b*C_ + c)*IMG_ + ph*P_ + r)*IMG_ + pw*P_ + col];
}

// ---------------- assemble h = concat(cls, tok) + pos ----------------
__global__ void assemble_k(const float* __restrict__ tok, const float* __restrict__ cls,
                           const float* __restrict__ pos, float* __restrict__ h) {
    int idx = blockIdx.x * blockDim.x + threadIdx.x;
    if (idx >= T_*D_) return;
    int t = idx / D_, d = idx - t*D_;
    int b = t / S_, s = t - b*S_;
    float v = (s == 0) ? cls[d] : tok[(size_t)(b*NP_ + s - 1)*D_ + d];
    h[idx] = v + pos[s*D_ + d];
}

// ---------------- layernorm: one warp per row, cols=384 ----------------
__global__ void ln_k(const float* __restrict__ in, float* __restrict__ out,
                     const float* __restrict__ g, const float* __restrict__ bta,
                     int rows, int instride) {
    int warp = (blockIdx.x * blockDim.x + threadIdx.x) >> 5;
    int lane = threadIdx.x & 31;
    if (warp >= rows) return;
    const float* row = in + (size_t)warp * instride;
    float v[12];
    float s = 0.f;
#pragma unroll
    for (int i = 0; i < 12; i++) { v[i] = row[lane + i*32]; s += v[i]; }
#pragma unroll
    for (int o = 16; o > 0; o >>= 1) s += __shfl_xor_sync(0xffffffffu, s, o);
    float mean = s * (1.f/384.f);
    float vs = 0.f;
#pragma unroll
    for (int i = 0; i < 12; i++) { float d = v[i] - mean; vs += d*d; }
#pragma unroll
    for (int o = 16; o > 0; o >>= 1) vs += __shfl_xor_sync(0xffffffffu, vs, o);
    float rstd = rsqrtf(vs * (1.f/384.f) + 1e-5f);
    float* orow = out + (size_t)warp * D_;
#pragma unroll
    for (int i = 0; i < 12; i++) {
        int c = lane + i*32;
        orow[c] = (v[i] - mean) * rstd * g[c] + bta[c];
    }
}

// ---------------- generic SGEMM: C[M,N] = A[M,K] @ W[N,K]^T (+bias)(+gelu)(+resid)
// MODE 0: store   MODE 1: resid add   MODE 2: gelu
template <int MODE>
__global__ void __launch_bounds__(256)
gemm_k(const float* __restrict__ A, const float* __restrict__ W,
       const float* __restrict__ bias, const float* __restrict__ resid,
       float* __restrict__ C, int M, int N, int K) {
    __shared__ float As[8][132];
    __shared__ float Bs[8][132];
    int tid = threadIdx.x;
    int m0 = blockIdx.y * 128, n0 = blockIdx.x * 128;
    int ty = tid >> 4, tx = tid & 15;
    int lr = tid >> 1;
    int lk = (tid & 1) * 4;
    float acc[8][8];
#pragma unroll
    for (int i = 0; i < 8; i++)
#pragma unroll
        for (int j = 0; j < 8; j++) acc[i][j] = 0.f;

    bool av = (m0 + lr) < M;
    bool wv = (n0 + lr) < N;
    const float* Aptr = A + (size_t)(m0 + lr) * K + lk;
    const float* Wptr = W + (size_t)(n0 + lr) * K + lk;

    for (int k0 = 0; k0 < K; k0 += 8) {
        float4 va = av ? *(const float4*)(Aptr + k0) : make_float4(0.f,0.f,0.f,0.f);
        float4 vb = wv ? *(const float4*)(Wptr + k0) : make_float4(0.f,0.f,0.f,0.f);
        __syncthreads();
        As[lk+0][lr] = va.x; As[lk+1][lr] = va.y; As[lk+2][lr] = va.z; As[lk+3][lr] = va.w;
        Bs[lk+0][lr] = vb.x; Bs[lk+1][lr] = vb.y; Bs[lk+2][lr] = vb.z; Bs[lk+3][lr] = vb.w;
        __syncthreads();
#pragma unroll
        for (int k = 0; k < 8; k++) {
            float a[8], b[8];
#pragma unroll
            for (int i = 0; i < 8; i++) a[i] = As[k][ty*8 + i];
#pragma unroll
            for (int j = 0; j < 8; j++) b[j] = Bs[k][tx*8 + j];
#pragma unroll
            for (int i = 0; i < 8; i++)
#pragma unroll
                for (int j = 0; j < 8; j++) acc[i][j] += a[i] * b[j];
        }
    }
#pragma unroll
    for (int i = 0; i < 8; i++) {
        int gm = m0 + ty*8 + i;
        if (gm >= M) continue;
#pragma unroll
        for (int j = 0; j < 8; j++) {
            int gn = n0 + tx*8 + j;
            if (gn >= N) continue;
            float v = acc[i][j];
            if (bias) v += bias[gn];
            if (MODE == 2) v = 0.5f * v * (1.f + erff(v * 0.70710678118654752f));
            if (MODE == 1) v += resid[(size_t)gm * N + gn];
            C[(size_t)gm * N + gn] = v;
        }
    }
}

// ---------------- fused attention: block = (32 q rows, one (b,h)) ----------------
__global__ void __launch_bounds__(256)
attn_k(const float* __restrict__ qkv, float* __restrict__ ctx) {
    __shared__ float Ks[64*64];   // float4-swizzled along d
    __shared__ float Vs[64*64];   // plain row-major
    __shared__ float Ss[32*64];   // p, swizzled kk^(8*(q&7))

    int tid = threadIdx.x;
    int q0 = blockIdx.x * 32;
    int bh = blockIdx.y;
    int b = bh / HEADS_, hh = bh - b*HEADS_;
    const float* base = qkv + (size_t)b * S_ * TRID_ + hh * HD_;

    int q = tid >> 3, lane8 = tid & 7;
    int qg = q0 + q;
    int qsw = (q & 7) << 3;

    // Q row in registers, pre-scaled by 1/sqrt(64)
    float qreg[64];
    if (qg < S_) {
        const float* qrow = base + (size_t)qg * TRID_;
#pragma unroll
        for (int d4 = 0; d4 < 16; d4++) {
            float4 v = *(const float4*)(qrow + d4*4);
            qreg[d4*4+0] = v.x * 0.125f; qreg[d4*4+1] = v.y * 0.125f;
            qreg[d4*4+2] = v.z * 0.125f; qreg[d4*4+3] = v.w * 0.125f;
        }
    } else {
#pragma unroll
        for (int d = 0; d < 64; d++) qreg[d] = 0.f;
    }

    float O[8];
#pragma unroll
    for (int e = 0; e < 8; e++) O[e] = 0.f;
    float m = -1e30f, l = 0.f;

    for (int kt = 0; kt < 4; kt++) {
        __syncthreads();
#pragma unroll
        for (int j = 0; j < 4; j++) {
            int lin = tid + j*256;
            int kk = lin >> 4, d4 = lin & 15;
            int kg = kt*64 + kk;
            float4 kv = make_float4(0.f,0.f,0.f,0.f);
            float4 vv = make_float4(0.f,0.f,0.f,0.f);
            if (kg < S_) {
                kv = *(const float4*)(base + D_  + (size_t)kg * TRID_ + d4*4);
                vv = *(const float4*)(base + 2*D_ + (size_t)kg * TRID_ + d4*4);
            }
            *(float4*)&Ks[kk*64 + ((d4 + kk) & 15) * 4] = kv;
            *(float4*)&Vs[kk*64 + d4*4] = vv;
        }
        __syncthreads();

        // scores for 8 kk per thread
        float s[8];
#pragma unroll
        for (int j = 0; j < 8; j++) {
            int kk = lane8 + j*8;
            float acc = 0.f;
#pragma unroll
            for (int d4 = 0; d4 < 16; d4++) {
                float4 kv = *(const float4*)&Ks[kk*64 + ((d4 + kk) & 15) * 4];
                acc += qreg[d4*4+0]*kv.x + qreg[d4*4+1]*kv.y
                     + qreg[d4*4+2]*kv.z + qreg[d4*4+3]*kv.w;
            }
            int kg = kt*64 + kk;
            s[j] = (kg < S_) ? acc : -1e30f;
        }
        // row max over 8 regs + 8 lanes
        float mt = s[0];
#pragma unroll
        for (int j = 1; j < 8; j++) mt = fmaxf(mt, s[j]);
        mt = fmaxf(mt, __shfl_xor_sync(0xffffffffu, mt, 4, 8));
        mt = fmaxf(mt, __shfl_xor_sync(0xffffffffu, mt, 2, 8));
        mt = fmaxf(mt, __shfl_xor_sync(0xffffffffu, mt, 1, 8));
        float mn = fmaxf(m, mt);
        float r = __expf(m - mn);
        float p[8];
        float ls = 0.f;
#pragma unroll
        for (int j = 0; j < 8; j++) { p[j] = __expf(s[j] - mn); ls += p[j]; }
        ls += __shfl_xor_sync(0xffffffffu, ls, 4, 8);
        ls += __shfl_xor_sync(0xffffffffu, ls, 2, 8);
        ls += __shfl_xor_sync(0xffffffffu, ls, 1, 8);
        l = l * r + ls;
        m = mn;
#pragma unroll
        for (int j = 0; j < 8; j++) {
            int kk = lane8 + j*8;
            Ss[q*64 + (kk ^ qsw)] = p[j];
        }
        __syncwarp();
#pragma unroll
        for (int e = 0; e < 8; e++) O[e] *= r;
#pragma unroll
        for (int kk = 0; kk < 64; kk++) {
            float pv = Ss[q*64 + (kk ^ qsw)];
            float4 v0 = *(const float4*)&Vs[kk*64 + lane8*8];
            float4 v1 = *(const float4*)&Vs[kk*64 + lane8*8 + 4];
            O[0] += pv * v0.x; O[1] += pv * v0.y; O[2] += pv * v0.z; O[3] += pv * v0.w;
            O[4] += pv * v1.x; O[5] += pv * v1.y; O[6] += pv * v1.z; O[7] += pv * v1.w;
        }
    }

    if (qg < S_) {
        float inv = 1.f / l;
        float* orow = ctx + (size_t)(b * S_ + qg) * D_ + hh * HD_ + lane8*8;
        float4 o0 = make_float4(O[0]*inv, O[1]*inv, O[2]*inv, O[3]*inv);
        float4 o1 = make_float4(O[4]*inv, O[5]*inv, O[6]*inv, O[7]*inv);
        *(float4*)orow = o0;
        *(float4*)(orow + 4) = o1;
    }
}

// ---------------- launch ----------------
extern "C" void kernel_launch(void* const* d_in, const int* in_sizes, int n_in,
                              void* d_out, int out_size) {
    const float* x         = (const float*)d_in[0];
    const float* patch_w   = (const float*)d_in[1];
    const float* patch_b   = (const float*)d_in[2];
    const float* cls_token = (const float*)d_in[3];
    const float* pos_embed = (const float*)d_in[4];
    const float* ln1_g     = (const float*)d_in[5];
    const float* ln1_b     = (const float*)d_in[6];
    const float* qkv_w     = (const float*)d_in[7];
    const float* qkv_b     = (const float*)d_in[8];
    const float* out_w     = (const float*)d_in[9];
    const float* out_b     = (const float*)d_in[10];
    const float* ln2_g     = (const float*)d_in[11];
    const float* ln2_b     = (const float*)d_in[12];
    const float* fc1_w     = (const float*)d_in[13];
    const float* fc1_b     = (const float*)d_in[14];
    const float* fc2_w     = (const float*)d_in[15];
    const float* fc2_b     = (const float*)d_in[16];
    const float* lnf_g     = (const float*)d_in[17];
    const float* lnf_b     = (const float*)d_in[18];
    const float* head_w    = (const float*)d_in[19];
    float* out = (float*)d_out;

    float *patches, *tok, *h, *xn, *qkv, *ctx, *hid, *cls;
    cudaGetSymbolAddress((void**)&patches, g_patches);
    cudaGetSymbolAddress((void**)&tok,     g_tok);
    cudaGetSymbolAddress((void**)&h,       g_h);
    cudaGetSymbolAddress((void**)&xn,      g_xn);
    cudaGetSymbolAddress((void**)&qkv,     g_qkv);
    cudaGetSymbolAddress((void**)&ctx,     g_ctx);
    cudaGetSymbolAddress((void**)&hid,     g_hid);
    cudaGetSymbolAddress((void**)&cls,     g_cls);

    // patch embed
    patchify_k<<<(BT_*PD_ + 255)/256, 256>>>(x, patches);
    gemm_k<0><<<dim3(D_/128, BT_/128), 256>>>(patches, patch_w, patch_b, nullptr, tok,
                                              BT_, D_, PD_);
    assemble_k<<<(T_*D_ + 255)/256, 256>>>(tok, cls_token, pos_embed, h);

    const int lnBlocks = (T_ + 7) / 8;   // 8 warps/block, warp per row
    for (int L = 0; L < DEPTH_; L++) {
        ln_k<<<lnBlocks, 256>>>(h, xn, ln1_g + L*D_, ln1_b + L*D_, T_, D_);
        gemm_k<0><<<dim3(TRID_/128, T_/128), 256>>>(xn, qkv_w + (size_t)L*TRID_*D_,
                                                    qkv_b + L*TRID_, nullptr, qkv,
                                                    T_, TRID_, D_);
        attn_k<<<dim3(7, B_*HEADS_), 256>>>(qkv, ctx);
        gemm_k<1><<<dim3(D_/128, T_/128), 256>>>(ctx, out_w + (size_t)L*D_*D_,
                                                 out_b + L*D_, h, h,
                                                 T_, D_, D_);
        ln_k<<<lnBlocks, 256>>>(h, xn, ln2_g + L*D_, ln2_b + L*D_, T_, D_);
        gemm_k<2><<<dim3(HID_/128, T_/128), 256>>>(xn, fc1_w + (size_t)L*HID_*D_,
                                                   fc1_b + L*HID_, nullptr, hid,
                                                   T_, HID_, D_);
        gemm_k<1><<<dim3(D_/128, T_/128), 256>>>(hid, fc2_w + (size_t)L*D_*HID_,
                                                 fc2_b + L*D_, h, h,
                                                 T_, D_, HID_);
    }

    // final LN on cls tokens (row stride S*D) + head
    ln_k<<<(B_ + 7)/8, 256>>>(h, cls, lnf_g, lnf_b, B_, S_*D_);
    gemm_k<0><<<dim3(1, 1), 256>>>(cls, head_w, nullptr, nullptr, out,
                                   B_, NCLS_, D_);
}

// round 2
// speedup vs baseline: 1.0069x; 1.0069x over previous
#include <cuda_runtime.h>
#include <cstdint>
#include <cstddef>

#define B_     128
#define C_     3
#define IMG_   224
#define P_     16
#define HP_    14
#define NP_    196
#define S_     197
#define D_     384
#define HEADS_ 6
#define HD_    64
#define DEPTH_ 12
#define HID_   1536
#define NCLS_  100
#define PD_    768
#define T_     (B_*S_)    // 25216
#define BT_    (B_*NP_)   // 25088
#define TRID_  (3*D_)     // 1152

typedef unsigned long long ull;

__device__ __forceinline__ void ffma2(ull& acc, ull a, ull b) {
    asm("fma.rn.f32x2 %0, %1, %2, %0;" : "+l"(acc) : "l"(a), "l"(b));
}
__device__ __forceinline__ ull packdup(float a) {
    ull r; asm("mov.b64 %0, {%1, %1};" : "=l"(r) : "f"(a)); return r;
}
__device__ __forceinline__ ull pack2(float lo, float hi) {
    ull r; asm("mov.b64 %0, {%1, %2};" : "=l"(r) : "f"(lo), "f"(hi)); return r;
}
__device__ __forceinline__ void unpack2(ull v, float& lo, float& hi) {
    asm("mov.b64 {%0, %1}, %2;" : "=f"(lo), "=f"(hi) : "l"(v));
}
__device__ __forceinline__ void mul2(ull& v, ull s) {
    asm("mul.rn.f32x2 %0, %1, %2;" : "=l"(v) : "l"(v), "l"(s));
}

// ---------------- scratch (static device globals; no allocation) ----------------
__device__ float g_patches[(size_t)BT_*PD_];
__device__ float g_tok[(size_t)BT_*D_];
__device__ float g_h[(size_t)T_*D_];
__device__ float g_xn[(size_t)T_*D_];
__device__ float g_qkv[(size_t)T_*TRID_];
__device__ float g_ctx[(size_t)T_*D_];
__device__ float g_hid[(size_t)T_*HID_];
__device__ float g_cls[B_*D_];

// ---------------- patchify ----------------
__global__ void patchify_k(const float* __restrict__ x, float* __restrict__ out) {
    int idx = blockIdx.x * blockDim.x + threadIdx.x;
    if (idx >= BT_*PD_) return;
    int t = idx / PD_, j = idx - t*PD_;
    int b = t / NP_, p = t - b*NP_;
    int ph = p / HP_, pw = p - ph*HP_;
    int c = j >> 8, r = (j >> 4) & 15, col = j & 15;
    out[idx] = x[(((size_t)b*C_ + c)*IMG_ + ph*P_ + r)*IMG_ + pw*P_ + col];
}

// ---------------- assemble h = concat(cls, tok) + pos ----------------
__global__ void assemble_k(const float* __restrict__ tok, const float* __restrict__ cls,
                           const float* __restrict__ pos, float* __restrict__ h) {
    int idx = blockIdx.x * blockDim.x + threadIdx.x;
    if (idx >= T_*D_) return;
    int t = idx / D_, d = idx - t*D_;
    int b = t / S_, s = t - b*S_;
    float v = (s == 0) ? cls[d] : tok[(size_t)(b*NP_ + s - 1)*D_ + d];
    h[idx] = v + pos[s*D_ + d];
}

// ---------------- layernorm: one warp per row, cols=384 ----------------
__global__ void ln_k(const float* __restrict__ in, float* __restrict__ out,
                     const float* __restrict__ g, const float* __restrict__ bta,
                     int rows, int instride) {
    int warp = (blockIdx.x * blockDim.x + threadIdx.x) >> 5;
    int lane = threadIdx.x & 31;
    if (warp >= rows) return;
    const float* row = in + (size_t)warp * instride;
    float v[12];
    float s = 0.f;
#pragma unroll
    for (int i = 0; i < 12; i++) { v[i] = row[lane + i*32]; s += v[i]; }
#pragma unroll
    for (int o = 16; o > 0; o >>= 1) s += __shfl_xor_sync(0xffffffffu, s, o);
    float mean = s * (1.f/384.f);
    float vs = 0.f;
#pragma unroll
    for (int i = 0; i < 12; i++) { float d = v[i] - mean; vs += d*d; }
#pragma unroll
    for (int o = 16; o > 0; o >>= 1) vs += __shfl_xor_sync(0xffffffffu, vs, o);
    float rstd = rsqrtf(vs * (1.f/384.f) + 1e-5f);
    float* orow = out + (size_t)warp * D_;
#pragma unroll
    for (int i = 0; i < 12; i++) {
        int c = lane + i*32;
        orow[c] = (v[i] - mean) * rstd * g[c] + bta[c];
    }
}

// ---------------- FFMA2 SGEMM: C[M,N] = A[M,K] @ W[N,K]^T (+bias)(+gelu)(+resid)
// MODE 0: store   MODE 1: resid add   MODE 2: gelu
// 128x128 block, K-tile 16, double-buffered, packed f32x2 math (exact fp32).
template <int MODE>
__global__ void __launch_bounds__(256)
gemm_k(const float* __restrict__ A, const float* __restrict__ W,
       const float* __restrict__ bias, const float* __restrict__ resid,
       float* __restrict__ C, int M, int N, int K) {
    __shared__ float As[2][16][132];
    __shared__ float Bs[2][16][132];
    int tid = threadIdx.x;
    int m0 = blockIdx.y * 128, n0 = blockIdx.x * 128;
    int ty = tid >> 4, tx = tid & 15;
    int lr = tid >> 1;              // 0..127 row
    int lk = (tid & 1) * 4;         // k offset 0 or 4; second float4 at lk+8

    ull acc[8][4];
#pragma unroll
    for (int i = 0; i < 8; i++)
#pragma unroll
        for (int j = 0; j < 4; j++) acc[i][j] = 0ull;

    bool av = (m0 + lr) < M;
    bool wv = (n0 + lr) < N;
    const float* Aptr = A + (size_t)(m0 + lr) * K + lk;
    const float* Wptr = W + (size_t)(n0 + lr) * K + lk;
    const float4 z4 = make_float4(0.f,0.f,0.f,0.f);

    int ntiles = K >> 4;

    // prologue: tile 0 -> buf 0
    {
        float4 va0 = av ? *(const float4*)(Aptr)     : z4;
        float4 va1 = av ? *(const float4*)(Aptr + 8) : z4;
        float4 vb0 = wv ? *(const float4*)(Wptr)     : z4;
        float4 vb1 = wv ? *(const float4*)(Wptr + 8) : z4;
        As[0][lk+0][lr]=va0.x; As[0][lk+1][lr]=va0.y; As[0][lk+2][lr]=va0.z; As[0][lk+3][lr]=va0.w;
        As[0][lk+8][lr]=va1.x; As[0][lk+9][lr]=va1.y; As[0][lk+10][lr]=va1.z; As[0][lk+11][lr]=va1.w;
        Bs[0][lk+0][lr]=vb0.x; Bs[0][lk+1][lr]=vb0.y; Bs[0][lk+2][lr]=vb0.z; Bs[0][lk+3][lr]=vb0.w;
        Bs[0][lk+8][lr]=vb1.x; Bs[0][lk+9][lr]=vb1.y; Bs[0][lk+10][lr]=vb1.z; Bs[0][lk+11][lr]=vb1.w;
    }
    __syncthreads();

    for (int tile = 0; tile < ntiles; tile++) {
        int buf = tile & 1;
        bool pf = (tile + 1) < ntiles;
        float4 pa0, pa1, pb0, pb1;
        if (pf) {
            int k0 = (tile + 1) << 4;
            pa0 = av ? *(const float4*)(Aptr + k0)     : z4;
            pa1 = av ? *(const float4*)(Aptr + k0 + 8) : z4;
            pb0 = wv ? *(const float4*)(Wptr + k0)     : z4;
            pb1 = wv ? *(const float4*)(Wptr + k0 + 8) : z4;
        }
        const float (*Ac)[132] = As[buf];
        const float (*Bc)[132] = Bs[buf];
#pragma unroll
        for (int k = 0; k < 16; k++) {
            float4 a0 = *(const float4*)&Ac[k][ty*8];
            float4 a1 = *(const float4*)&Ac[k][ty*8 + 4];
            ulonglong2 b0 = *(const ulonglong2*)&Bc[k][tx*8];
            ulonglong2 b1 = *(const ulonglong2*)&Bc[k][tx*8 + 4];
            ull ap[8];
            ap[0]=packdup(a0.x); ap[1]=packdup(a0.y); ap[2]=packdup(a0.z); ap[3]=packdup(a0.w);
            ap[4]=packdup(a1.x); ap[5]=packdup(a1.y); ap[6]=packdup(a1.z); ap[7]=packdup(a1.w);
#pragma unroll
            for (int i = 0; i < 8; i++) {
                ffma2(acc[i][0], ap[i], b0.x);
                ffma2(acc[i][1], ap[i], b0.y);
                ffma2(acc[i][2], ap[i], b1.x);
                ffma2(acc[i][3], ap[i], b1.y);
            }
        }
        if (pf) {
            int nb = buf ^ 1;
            As[nb][lk+0][lr]=pa0.x; As[nb][lk+1][lr]=pa0.y; As[nb][lk+2][lr]=pa0.z; As[nb][lk+3][lr]=pa0.w;
            As[nb][lk+8][lr]=pa1.x; As[nb][lk+9][lr]=pa1.y; As[nb][lk+10][lr]=pa1.z; As[nb][lk+11][lr]=pa1.w;
            Bs[nb][lk+0][lr]=pb0.x; Bs[nb][lk+1][lr]=pb0.y; Bs[nb][lk+2][lr]=pb0.z; Bs[nb][lk+3][lr]=pb0.w;
            Bs[nb][lk+8][lr]=pb1.x; Bs[nb][lk+9][lr]=pb1.y; Bs[nb][lk+10][lr]=pb1.z; Bs[nb][lk+11][lr]=pb1.w;
        }
        __syncthreads();
    }

#pragma unroll
    for (int i = 0; i < 8; i++) {
        int gm = m0 + ty*8 + i;
        if (gm >= M) continue;
#pragma unroll
        for (int j2 = 0; j2 < 4; j2++) {
            float vlo, vhi;
            unpack2(acc[i][j2], vlo, vhi);
            float vv[2] = {vlo, vhi};
#pragma unroll
            for (int u = 0; u < 2; u++) {
                int gn = n0 + tx*8 + j2*2 + u;
                if (gn >= N) continue;
                float v = vv[u];
                if (bias) v += bias[gn];
                if (MODE == 2) v = 0.5f * v * (1.f + erff(v * 0.70710678118654752f));
                if (MODE == 1) v += resid[(size_t)gm * N + gn];
                C[(size_t)gm * N + gn] = v;
            }
        }
    }
}

// ---------------- fused attention: block = (32 q rows, one (b,h)) ----------------
__global__ void __launch_bounds__(256)
attn_k(const float* __restrict__ qkv, float* __restrict__ ctx) {
    __shared__ float Ks[64*64];   // float4-swizzled along d
    __shared__ float Vs[64*64];   // plain row-major
    __shared__ float Ss[32*64];   // p, swizzled kk^(8*(q&7))

    int tid = threadIdx.x;
    int q0 = blockIdx.x * 32;
    int bh = blockIdx.y;
    int b = bh / HEADS_, hh = bh - b*HEADS_;
    const float* base = qkv + (size_t)b * S_ * TRID_ + hh * HD_;

    int q = tid >> 3, lane8 = tid & 7;
    int qg = q0 + q;
    int qsw = (q & 7) << 3;

    // Q row packed into f32x2 pairs, pre-scaled by 1/sqrt(64)
    ull qp[32];
    if (qg < S_) {
        const float* qrow = base + (size_t)qg * TRID_;
#pragma unroll
        for (int d4 = 0; d4 < 16; d4++) {
            float4 v = *(const float4*)(qrow + d4*4);
            qp[2*d4]   = pack2(v.x * 0.125f, v.y * 0.125f);
            qp[2*d4+1] = pack2(v.z * 0.125f, v.w * 0.125f);
        }
    } else {
#pragma unroll
        for (int d = 0; d < 32; d++) qp[d] = 0ull;
    }

    ull Op[4];
#pragma unroll
    for (int e = 0; e < 4; e++) Op[e] = 0ull;
    float m = -1e30f, l = 0.f;

    for (int kt = 0; kt < 4; kt++) {
        __syncthreads();
#pragma unroll
        for (int j = 0; j < 4; j++) {
            int lin = tid + j*256;
            int kk = lin >> 4, d4 = lin & 15;
            int kg = kt*64 + kk;
            float4 kv = make_float4(0.f,0.f,0.f,0.f);
            float4 vv = make_float4(0.f,0.f,0.f,0.f);
            if (kg < S_) {
                kv = *(const float4*)(base + D_  + (size_t)kg * TRID_ + d4*4);
                vv = *(const float4*)(base + 2*D_ + (size_t)kg * TRID_ + d4*4);
            }
            *(float4*)&Ks[kk*64 + ((d4 + kk) & 15) * 4] = kv;
            *(float4*)&Vs[kk*64 + d4*4] = vv;
        }
        __syncthreads();

        // scores for 8 kk per thread (f32x2 dot)
        float s[8];
#pragma unroll
        for (int j = 0; j < 8; j++) {
            int kk = lane8 + j*8;
            ull sp = 0ull;
#pragma unroll
            for (int d4 = 0; d4 < 16; d4++) {
                ulonglong2 kv = *(const ulonglong2*)&Ks[kk*64 + ((d4 + kk) & 15) * 4];
                ffma2(sp, qp[2*d4],   kv.x);
                ffma2(sp, qp[2*d4+1], kv.y);
            }
            float lo, hi; unpack2(sp, lo, hi);
            int kg = kt*64 + kk;
            s[j] = (kg < S_) ? (lo + hi) : -1e30f;
        }
        float mt = s[0];
#pragma unroll
        for (int j = 1; j < 8; j++) mt = fmaxf(mt, s[j]);
        mt = fmaxf(mt, __shfl_xor_sync(0xffffffffu, mt, 4, 8));
        mt = fmaxf(mt, __shfl_xor_sync(0xffffffffu, mt, 2, 8));
        mt = fmaxf(mt, __shfl_xor_sync(0xffffffffu, mt, 1, 8));
        float mn = fmaxf(m, mt);
        float r = __expf(m - mn);
        float p[8];
        float ls = 0.f;
#pragma unroll
        for (int j = 0; j < 8; j++) { p[j] = __expf(s[j] - mn); ls += p[j]; }
        ls += __shfl_xor_sync(0xffffffffu, ls, 4, 8);
        ls += __shfl_xor_sync(0xffffffffu, ls, 2, 8);
        ls += __shfl_xor_sync(0xffffffffu, ls, 1, 8);
        l = l * r + ls;
        m = mn;
#pragma unroll
        for (int j = 0; j < 8; j++) {
            int kk = lane8 + j*8;
            Ss[q*64 + (kk ^ qsw)] = p[j];
        }
        __syncwarp();
        ull rd = packdup(r);
#pragma unroll
        for (int e = 0; e < 4; e++) mul2(Op[e], rd);
#pragma unroll
        for (int kk = 0; kk < 64; kk++) {
            ull pv = packdup(Ss[q*64 + (kk ^ qsw)]);
            ulonglong2 v0 = *(const ulonglong2*)&Vs[kk*64 + lane8*8];
            ulonglong2 v1 = *(const ulonglong2*)&Vs[kk*64 + lane8*8 + 4];
            ffma2(Op[0], pv, v0.x);
            ffma2(Op[1], pv, v0.y);
            ffma2(Op[2], pv, v1.x);
            ffma2(Op[3], pv, v1.y);
        }
    }

    if (qg < S_) {
        float inv = 1.f / l;
        float O[8];
#pragma unroll
        for (int e = 0; e < 4; e++) unpack2(Op[e], O[2*e], O[2*e+1]);
        float* orow = ctx + (size_t)(b * S_ + qg) * D_ + hh * HD_ + lane8*8;
        float4 o0 = make_float4(O[0]*inv, O[1]*inv, O[2]*inv, O[3]*inv);
        float4 o1 = make_float4(O[4]*inv, O[5]*inv, O[6]*inv, O[7]*inv);
        *(float4*)orow = o0;
        *(float4*)(orow + 4) = o1;
    }
}

// ---------------- launch ----------------
extern "C" void kernel_launch(void* const* d_in, const int* in_sizes, int n_in,
                              void* d_out, int out_size) {
    const float* x         = (const float*)d_in[0];
    const float* patch_w   = (const float*)d_in[1];
    const float* patch_b   = (const float*)d_in[2];
    const float* cls_token = (const float*)d_in[3];
    const float* pos_embed = (const float*)d_in[4];
    const float* ln1_g     = (const float*)d_in[5];
    const float* ln1_b     = (const float*)d_in[6];
    const float* qkv_w     = (const float*)d_in[7];
    const float* qkv_b     = (const float*)d_in[8];
    const float* out_w     = (const float*)d_in[9];
    const float* out_b     = (const float*)d_in[10];
    const float* ln2_g     = (const float*)d_in[11];
    const float* ln2_b     = (const float*)d_in[12];
    const float* fc1_w     = (const float*)d_in[13];
    const float* fc1_b     = (const float*)d_in[14];
    const float* fc2_w     = (const float*)d_in[15];
    const float* fc2_b     = (const float*)d_in[16];
    const float* lnf_g     = (const float*)d_in[17];
    const float* lnf_b     = (const float*)d_in[18];
    const float* head_w    = (const float*)d_in[19];
    float* out = (float*)d_out;

    float *patches, *tok, *h, *xn, *qkv, *ctx, *hid, *cls;
    cudaGetSymbolAddress((void**)&patches, g_patches);
    cudaGetSymbolAddress((void**)&tok,     g_tok);
    cudaGetSymbolAddress((void**)&h,       g_h);
    cudaGetSymbolAddress((void**)&xn,      g_xn);
    cudaGetSymbolAddress((void**)&qkv,     g_qkv);
    cudaGetSymbolAddress((void**)&ctx,     g_ctx);
    cudaGetSymbolAddress((void**)&hid,     g_hid);
    cudaGetSymbolAddress((void**)&cls,     g_cls);

    // patch embed
    patchify_k<<<(BT_*PD_ + 255)/256, 256>>>(x, patches);
    gemm_k<0><<<dim3(D_/128, BT_/128), 256>>>(patches, patch_w, patch_b, nullptr, tok,
                                              BT_, D_, PD_);
    assemble_k<<<(T_*D_ + 255)/256, 256>>>(tok, cls_token, pos_embed, h);

    const int lnBlocks = (T_ + 7) / 8;
    for (int L = 0; L < DEPTH_; L++) {
        ln_k<<<lnBlocks, 256>>>(h, xn, ln1_g + L*D_, ln1_b + L*D_, T_, D_);
        gemm_k<0><<<dim3(TRID_/128, T_/128), 256>>>(xn, qkv_w + (size_t)L*TRID_*D_,
                                                    qkv_b + L*TRID_, nullptr, qkv,
                                                    T_, TRID_, D_);
        attn_k<<<dim3(7, B_*HEADS_), 256>>>(qkv, ctx);
        gemm_k<1><<<dim3(D_/128, T_/128), 256>>>(ctx, out_w + (size_t)L*D_*D_,
                                                 out_b + L*D_, h, h,
                                                 T_, D_, D_);
        ln_k<<<lnBlocks, 256>>>(h, xn, ln2_g + L*D_, ln2_b + L*D_, T_, D_);
        gemm_k<2><<<dim3(HID_/128, T_/128), 256>>>(xn, fc1_w + (size_t)L*HID_*D_,
                                                   fc1_b + L*HID_, nullptr, hid,
                                                   T_, HID_, D_);
        gemm_k<1><<<dim3(D_/128, T_/128), 256>>>(hid, fc2_w + (size_t)L*D_*HID_,
                                                 fc2_b + L*D_, h, h,
                                                 T_, D_, HID_);
    }

    ln_k<<<(B_ + 7)/8, 256>>>(h, cls, lnf_g, lnf_b, B_, S_*D_);
    gemm_k<0><<<dim3(1, 1), 256>>>(cls, head_w, nullptr, nullptr, out,
                                   B_, NCLS_, D_);
}

// round 4
// speedup vs baseline: 1.6831x; 1.6716x over previous
#include <cuda_runtime.h>
#include <cuda_bf16.h>
#include <cstdint>
#include <cstddef>

#define B_     128
#define C_     3
#define IMG_   224
#define P_     16
#define HP_    14
#define NP_    196
#define S_     197
#define D_     384
#define HEADS_ 6
#define HD_    64
#define DEPTH_ 12
#define HID_   1536
#define NCLS_  100
#define PD_    768
#define T_     (B_*S_)    // 25216 = 197*128
#define BT_    (B_*NP_)   // 25088 = 196*128
#define TRID_  (3*D_)     // 1152

typedef unsigned long long ull;

// ===================== helpers =====================
__device__ __forceinline__ uint32_t smem_u32(const void* p) {
    uint32_t a;
    asm("{ .reg .u64 t; cvta.to.shared.u64 t, %1; cvt.u32.u64 %0, t; }" : "=r"(a) : "l"(p));
    return a;
}
__device__ __forceinline__ void cp16(uint32_t saddr, const void* g) {
    asm volatile("cp.async.cg.shared.global [%0], [%1], 16;" :: "r"(saddr), "l"(g));
}
#define CP_COMMIT() asm volatile("cp.async.commit_group;" ::: "memory")
#define CP_WAIT(n)  asm volatile("cp.async.wait_group %0;" :: "n"(n) : "memory")

__device__ __forceinline__ void ldsm4(uint32_t& r0, uint32_t& r1, uint32_t& r2, uint32_t& r3,
                                      uint32_t a) {
    asm volatile("ldmatrix.sync.aligned.m8n8.x4.shared.b16 {%0,%1,%2,%3}, [%4];"
                 : "=r"(r0), "=r"(r1), "=r"(r2), "=r"(r3) : "r"(a));
}
__device__ __forceinline__ void mma16816(float* c, uint32_t a0, uint32_t a1, uint32_t a2,
                                         uint32_t a3, uint32_t b0, uint32_t b1) {
    asm volatile("mma.sync.aligned.m16n8k16.row.col.f32.bf16.bf16.f32 "
                 "{%0,%1,%2,%3}, {%4,%5,%6,%7}, {%8,%9}, {%0,%1,%2,%3};"
                 : "+f"(c[0]), "+f"(c[1]), "+f"(c[2]), "+f"(c[3])
                 : "r"(a0), "r"(a1), "r"(a2), "r"(a3), "r"(b0), "r"(b1));
}

// f32x2 helpers for attention
__device__ __forceinline__ void ffma2(ull& acc, ull a, ull b) {
    asm("fma.rn.f32x2 %0, %1, %2, %0;" : "+l"(acc) : "l"(a), "l"(b));
}
__device__ __forceinline__ ull packdup(float a) {
    ull r; asm("mov.b64 %0, {%1, %1};" : "=l"(r) : "f"(a)); return r;
}
__device__ __forceinline__ ull pack2(float lo, float hi) {
    ull r; asm("mov.b64 %0, {%1, %2};" : "=l"(r) : "f"(lo), "f"(hi)); return r;
}
__device__ __forceinline__ void unpack2(ull v, float& lo, float& hi) {
    asm("mov.b64 {%0, %1}, %2;" : "=f"(lo), "=f"(hi) : "l"(v));
}
__device__ __forceinline__ void mul2(ull& v, ull s) {
    asm("mul.rn.f32x2 %0, %1, %2;" : "=l"(v) : "l"(v), "l"(s));
}
__device__ __forceinline__ void split_bf(float x, __nv_bfloat16& hi, __nv_bfloat16& lo) {
    hi = __float2bfloat16(x);
    lo = __float2bfloat16(x - __bfloat162float(hi));
}

// ===================== scratch =====================
__device__ float g_h[(size_t)T_*D_];
__device__ float g_tok[(size_t)BT_*D_];
__device__ float g_qkv[(size_t)T_*TRID_];
__device__ float g_cls[B_*D_];
__device__ __nv_bfloat16 g_x2[(size_t)T_*3*D_];
__device__ __nv_bfloat16 g_ctx2[(size_t)T_*3*D_];
__device__ __nv_bfloat16 g_hid2[(size_t)T_*3*HID_];
__device__ __nv_bfloat16 g_p2[(size_t)BT_*3*PD_];
__device__ __nv_bfloat16 g_pw2[(size_t)D_*3*PD_];
__device__ __nv_bfloat16 g_qkvw2[(size_t)DEPTH_*TRID_*3*D_];
__device__ __nv_bfloat16 g_outw2[(size_t)DEPTH_*D_*3*D_];
__device__ __nv_bfloat16 g_fc1w2[(size_t)DEPTH_*HID_*3*D_];
__device__ __nv_bfloat16 g_fc2w2[(size_t)DEPTH_*D_*3*HID_];

// ===================== weight split: [R,K] fp32 -> [R,3K] bf16 [hi,lo,hi] ===========
__global__ void wsplit_k(const float* __restrict__ src, __nv_bfloat16* __restrict__ dst,
                         int R, int K) {
    size_t idx = (size_t)blockIdx.x * blockDim.x + threadIdx.x;
    if (idx >= (size_t)R * K) return;
    int r = (int)(idx / K), k = (int)(idx - (size_t)r * K);
    __nv_bfloat16 hi, lo;
    split_bf(src[idx], hi, lo);
    size_t rb = (size_t)r * 3 * K;
    dst[rb + k] = hi;
    dst[rb + K + k] = lo;
    dst[rb + 2*K + k] = hi;
}

// ===================== patchify -> split [hi,hi,lo] =====================
__global__ void patchify_k(const float* __restrict__ x, __nv_bfloat16* __restrict__ out) {
    size_t idx = (size_t)blockIdx.x * blockDim.x + threadIdx.x;
    if (idx >= (size_t)BT_*PD_) return;
    int t = (int)(idx / PD_), j = (int)(idx - (size_t)t * PD_);
    int b = t / NP_, p = t - b*NP_;
    int ph = p / HP_, pw = p - ph*HP_;
    int c = j >> 8, r = (j >> 4) & 15, col = j & 15;
    float v = x[(((size_t)b*C_ + c)*IMG_ + ph*P_ + r)*IMG_ + pw*P_ + col];
    __nv_bfloat16 hi, lo;
    split_bf(v, hi, lo);
    size_t rb = (size_t)t * 3 * PD_;
    out[rb + j] = hi;
    out[rb + PD_ + j] = hi;
    out[rb + 2*PD_ + j] = lo;
}

// ===================== assemble =====================
__global__ void assemble_k(const float* __restrict__ tok, const float* __restrict__ cls,
                           const float* __restrict__ pos, float* __restrict__ h) {
    int idx = blockIdx.x * blockDim.x + threadIdx.x;
    if (idx >= T_*D_) return;
    int t = idx / D_, d = idx - t*D_;
    int b = t / S_, s = t - b*S_;
    float v = (s == 0) ? cls[d] : tok[(size_t)(b*NP_ + s - 1)*D_ + d];
    h[idx] = v + pos[s*D_ + d];
}

// ===================== layernorm =====================
template <int SPLIT>
__global__ void ln_k(const float* __restrict__ in, float* __restrict__ outf,
                     __nv_bfloat16* __restrict__ out2,
                     const float* __restrict__ g, const float* __restrict__ bta,
                     int rows, int instride) {
    int warp = (blockIdx.x * blockDim.x + threadIdx.x) >> 5;
    int lane = threadIdx.x & 31;
    if (warp >= rows) return;
    const float* row = in + (size_t)warp * instride;
    float v[12];
    float s = 0.f;
#pragma unroll
    for (int i = 0; i < 12; i++) { v[i] = row[lane + i*32]; s += v[i]; }
#pragma unroll
    for (int o = 16; o > 0; o >>= 1) s += __shfl_xor_sync(0xffffffffu, s, o);
    float mean = s * (1.f/384.f);
    float vs = 0.f;
#pragma unroll
    for (int i = 0; i < 12; i++) { float d = v[i] - mean; vs += d*d; }
#pragma unroll
    for (int o = 16; o > 0; o >>= 1) vs += __shfl_xor_sync(0xffffffffu, vs, o);
    float rstd = rsqrtf(vs * (1.f/384.f) + 1e-5f);
    if (SPLIT) {
        size_t rb = (size_t)warp * (3*D_);
#pragma unroll
        for (int i = 0; i < 12; i++) {
            int c = lane + i*32;
            float y = (v[i] - mean) * rstd * g[c] + bta[c];
            __nv_bfloat16 hi, lo;
            split_bf(y, hi, lo);
            out2[rb + c] = hi;
            out2[rb + D_ + c] = hi;
            out2[rb + 2*D_ + c] = lo;
        }
    } else {
        float* orow = outf + (size_t)warp * D_;
#pragma unroll
        for (int i = 0; i < 12; i++) {
            int c = lane + i*32;
            orow[c] = (v[i] - mean) * rstd * g[c] + bta[c];
        }
    }
}

// ===================== mma.sync bf16 GEMM =====================
// C[M,N] = A2[M,K2] @ W2[N,K2]^T (+bias)
// MODE 0: fp32 store. MODE 1: fp32 resid add. MODE 2: gelu -> split bf16 [hi,hi,lo].
// M,N multiples of 128; K2 multiple of 64. 8 warps, 2x4 warp grid, 64x32 warp tile.
#define GMM_SMEM 65536
template <int MODE>
__global__ void __launch_bounds__(256)
gemm_mma(const __nv_bfloat16* __restrict__ A, const __nv_bfloat16* __restrict__ W,
         const float* __restrict__ bias, const float* __restrict__ resid,
         void* __restrict__ Cout, int M, int N, int K2) {
    extern __shared__ char dsm[];
    uint32_t sbase = smem_u32(dsm);
    const uint32_t sA = sbase;            // 2 bufs x 16384
    const uint32_t sB = sbase + 32768;    // 2 bufs x 16384

    int tid = threadIdx.x;
    int wid = tid >> 5, lane = tid & 31;
    int wm = wid & 1, wn = wid >> 1;
    int m0 = blockIdx.y * 128, n0 = blockIdx.x * 128;

    // loader mapping: lin = tid + 256*i, row = lin>>3 (0..127), chunk c = tid&7
    int c = tid & 7;
    int r0w = tid >> 3;                   // base row; +32 per i
    const __nv_bfloat16* Ag = A + (size_t)(m0 + r0w) * K2 + c * 8;
    const __nv_bfloat16* Wg = W + (size_t)(n0 + r0w) * K2 + c * 8;
    uint32_t so[4];
#pragma unroll
    for (int i = 0; i < 4; i++) {
        int r = r0w + 32*i;
        so[i] = r*128 + ((c ^ (r & 7)) << 4);
    }

    float acc[4][4][4];
#pragma unroll
    for (int f = 0; f < 4; f++)
#pragma unroll
        for (int g = 0; g < 4; g++)
#pragma unroll
            for (int e = 0; e < 4; e++) acc[f][g][e] = 0.f;

    // precompute ldmatrix smem offsets (buf-relative)
    uint32_t aoff[4], boff[2];
#pragma unroll
    for (int f = 0; f < 4; f++) {
        int r = wm*64 + f*16 + (lane & 15);
        int kc = (lane >> 4);                 // k-half within step
        aoff[f] = r*128 + (((kc) ^ (r & 7)) << 4);   // ks adds (ks*2) to kc -> handled by XOR trick below
    }
#pragma unroll
    for (int g2 = 0; g2 < 2; g2++) {
        int nr = wn*32 + g2*16 + ((lane >> 4) << 3) + (lane & 7);
        int kc = (lane >> 3) & 1;
        boff[g2] = nr*128 + (((kc) ^ (nr & 7)) << 4);
    }
    // per-ks we need chunk index kc_total = ks*2 + kc_base. Since swizzle is XOR with (row&7),
    // and kc_total = kc_base + ks*2, recompute offsets per ks cheaply:
    // phys = (kc_total ^ (r&7))*16. We recompute fully per ks for correctness.

    int nc = K2 >> 6;

    // prefetch chunk 0 -> buf 0
#pragma unroll
    for (int i = 0; i < 4; i++) {
        cp16(sA + so[i], Ag + (size_t)(32*i) * K2);
        cp16(sB + so[i], Wg + (size_t)(32*i) * K2);
    }
    CP_COMMIT();

    for (int ch = 0; ch < nc; ch++) {
        int buf = ch & 1;
        if (ch + 1 < nc) {
            int nb = (ch + 1) & 1;
            const __nv_bfloat16* Agc = Ag + (size_t)(ch + 1) * 64;
            const __nv_bfloat16* Wgc = Wg + (size_t)(ch + 1) * 64;
#pragma unroll
            for (int i = 0; i < 4; i++) {
                cp16(sA + nb*16384 + so[i], Agc + (size_t)(32*i) * K2);
                cp16(sB + nb*16384 + so[i], Wgc + (size_t)(32*i) * K2);
            }
            CP_COMMIT();
            CP_WAIT(1);
        } else {
            CP_WAIT(0);
        }
        __syncthreads();

        uint32_t bufA = sA + buf*16384;
        uint32_t bufB = sB + buf*16384;
#pragma unroll
        for (int ks = 0; ks < 4; ks++) {
            uint32_t a[4][4];
#pragma unroll
            for (int f = 0; f < 4; f++) {
                int r = wm*64 + f*16 + (lane & 15);
                int kc = ks*2 + (lane >> 4);
                uint32_t addr = bufA + r*128 + ((kc ^ (r & 7)) << 4);
                ldsm4(a[f][0], a[f][1], a[f][2], a[f][3], addr);
            }
            uint32_t b[2][4];
#pragma unroll
            for (int g2 = 0; g2 < 2; g2++) {
                int nr = wn*32 + g2*16 + ((lane >> 4) << 3) + (lane & 7);
                int kc = ks*2 + ((lane >> 3) & 1);
                uint32_t addr = bufB + nr*128 + ((kc ^ (nr & 7)) << 4);
                ldsm4(b[g2][0], b[g2][1], b[g2][2], b[g2][3], addr);
            }
#pragma unroll
            for (int f = 0; f < 4; f++)
#pragma unroll
                for (int g = 0; g < 4; g++)
                    mma16816(acc[f][g], a[f][0], a[f][1], a[f][2], a[f][3],
                             b[g >> 1][(g & 1)*2], b[g >> 1][(g & 1)*2 + 1]);
        }
        __syncthreads();
    }

    // epilogue
#pragma unroll
    for (int f = 0; f < 4; f++) {
        int m = m0 + wm*64 + f*16 + (lane >> 2);
#pragma unroll
        for (int g = 0; g < 4; g++) {
            int n = n0 + wn*32 + g*8 + (lane & 3)*2;
            float bn0 = bias[n], bn1 = bias[n + 1];
            float v00 = acc[f][g][0] + bn0, v01 = acc[f][g][1] + bn1;
            float v10 = acc[f][g][2] + bn0, v11 = acc[f][g][3] + bn1;
            if (MODE == 1) {
                const float* r0p = resid + (size_t)m*N + n;
                const float* r1p = resid + (size_t)(m + 8)*N + n;
                v00 += r0p[0]; v01 += r0p[1];
                v10 += r1p[0]; v11 += r1p[1];
            }
            if (MODE == 2) {
                v00 = 0.5f * v00 * (1.f + erff(v00 * 0.70710678118654752f));
                v01 = 0.5f * v01 * (1.f + erff(v01 * 0.70710678118654752f));
                v10 = 0.5f * v10 * (1.f + erff(v10 * 0.70710678118654752f));
                v11 = 0.5f * v11 * (1.f + erff(v11 * 0.70710678118654752f));
                __nv_bfloat16* H = (__nv_bfloat16*)Cout;
                size_t rb0 = (size_t)m * (3*N), rb1 = (size_t)(m + 8) * (3*N);
                __nv_bfloat16 h0, l0, h1, l1;
                split_bf(v00, h0, l0); split_bf(v01, h1, l1);
                __nv_bfloat162 hh, llv;
                hh.x = h0; hh.y = h1; llv.x = l0; llv.y = l1;
                *(__nv_bfloat162*)(H + rb0 + n)       = hh;
                *(__nv_bfloat162*)(H + rb0 + N + n)   = hh;
                *(__nv_bfloat162*)(H + rb0 + 2*N + n) = llv;
                split_bf(v10, h0, l0); split_bf(v11, h1, l1);
                hh.x = h0; hh.y = h1; llv.x = l0; llv.y = l1;
                *(__nv_bfloat162*)(H + rb1 + n)       = hh;
                *(__nv_bfloat162*)(H + rb1 + N + n)   = hh;
                *(__nv_bfloat162*)(H + rb1 + 2*N + n) = llv;
            } else {
                float* Cf = (float*)Cout;
                *(float2*)(Cf + (size_t)m*N + n)       = make_float2(v00, v01);
                *(float2*)(Cf + (size_t)(m + 8)*N + n) = make_float2(v10, v11);
            }
        }
    }
}

// ===================== fp32 GEMM for head only =====================
__global__ void __launch_bounds__(256)
gemm32_k(const float* __restrict__ A, const float* __restrict__ W,
         float* __restrict__ C, int M, int N, int K) {
    __shared__ float As[8][132];
    __shared__ float Bs[8][132];
    int tid = threadIdx.x;
    int m0 = blockIdx.y * 128, n0 = blockIdx.x * 128;
    int ty = tid >> 4, tx = tid & 15;
    int lr = tid >> 1;
    int lk = (tid & 1) * 4;
    float acc[8][8];
#pragma unroll
    for (int i = 0; i < 8; i++)
#pragma unroll
        for (int j = 0; j < 8; j++) acc[i][j] = 0.f;
    bool av = (m0 + lr) < M;
    bool wv = (n0 + lr) < N;
    const float* Aptr = A + (size_t)(m0 + lr) * K + lk;
    const float* Wptr = W + (size_t)(n0 + lr) * K + lk;
    for (int k0 = 0; k0 < K; k0 += 8) {
        float4 va = av ? *(const float4*)(Aptr + k0) : make_float4(0.f,0.f,0.f,0.f);
        float4 vb = wv ? *(const float4*)(Wptr + k0) : make_float4(0.f,0.f,0.f,0.f);
        __syncthreads();
        As[lk+0][lr]=va.x; As[lk+1][lr]=va.y; As[lk+2][lr]=va.z; As[lk+3][lr]=va.w;
        Bs[lk+0][lr]=vb.x; Bs[lk+1][lr]=vb.y; Bs[lk+2][lr]=vb.z; Bs[lk+3][lr]=vb.w;
        __syncthreads();
#pragma unroll
        for (int k = 0; k < 8; k++) {
            float a[8], b[8];
#pragma unroll
            for (int i = 0; i < 8; i++) a[i] = As[k][ty*8 + i];
#pragma unroll
            for (int j = 0; j < 8; j++) b[j] = Bs[k][tx*8 + j];
#pragma unroll
            for (int i = 0; i < 8; i++)
#pragma unroll
                for (int j = 0; j < 8; j++) acc[i][j] += a[i] * b[j];
        }
    }
#pragma unroll
    for (int i = 0; i < 8; i++) {
        int gm = m0 + ty*8 + i;
        if (gm >= M) continue;
#pragma unroll
        for (int j = 0; j < 8; j++) {
            int gn = n0 + tx*8 + j;
            if (gn >= N) continue;
            C[(size_t)gm * N + gn] = acc[i][j];
        }
    }
}

// ===================== fused attention (fp32, split-bf16 epilogue) =====================
__global__ void __launch_bounds__(256)
attn_k(const float* __restrict__ qkv, __nv_bfloat16* __restrict__ ctx2) {
    __shared__ float Ks[64*64];
    __shared__ float Vs[64*64];
    __shared__ float Ss[32*64];

    int tid = threadIdx.x;
    int q0 = blockIdx.x * 32;
    int bh = blockIdx.y;
    int b = bh / HEADS_, hh = bh - b*HEADS_;
    const float* base = qkv + (size_t)b * S_ * TRID_ + hh * HD_;

    int q = tid >> 3, lane8 = tid & 7;
    int qg = q0 + q;
    int qsw = (q & 7) << 3;

    ull qp[32];
    if (qg < S_) {
        const float* qrow = base + (size_t)qg * TRID_;
#pragma unroll
        for (int d4 = 0; d4 < 16; d4++) {
            float4 v = *(const float4*)(qrow + d4*4);
            qp[2*d4]   = pack2(v.x * 0.125f, v.y * 0.125f);
            qp[2*d4+1] = pack2(v.z * 0.125f, v.w * 0.125f);
        }
    } else {
#pragma unroll
        for (int d = 0; d < 32; d++) qp[d] = 0ull;
    }

    ull Op[4];
#pragma unroll
    for (int e = 0; e < 4; e++) Op[e] = 0ull;
    float m = -1e30f, l = 0.f;

    for (int kt = 0; kt < 4; kt++) {
        __syncthreads();
#pragma unroll
        for (int j = 0; j < 4; j++) {
            int lin = tid + j*256;
            int kk = lin >> 4, d4 = lin & 15;
            int kg = kt*64 + kk;
            float4 kv = make_float4(0.f,0.f,0.f,0.f);
            float4 vv = make_float4(0.f,0.f,0.f,0.f);
            if (kg < S_) {
                kv = *(const float4*)(base + D_  + (size_t)kg * TRID_ + d4*4);
                vv = *(const float4*)(base + 2*D_ + (size_t)kg * TRID_ + d4*4);
            }
            *(float4*)&Ks[kk*64 + ((d4 + kk) & 15) * 4] = kv;
            *(float4*)&Vs[kk*64 + d4*4] = vv;
        }
        __syncthreads();

        float s[8];
#pragma unroll
        for (int j = 0; j < 8; j++) {
            int kk = lane8 + j*8;
            ull sp = 0ull;
#pragma unroll
            for (int d4 = 0; d4 < 16; d4++) {
                ulonglong2 kv = *(const ulonglong2*)&Ks[kk*64 + ((d4 + kk) & 15) * 4];
                ffma2(sp, qp[2*d4],   kv.x);
                ffma2(sp, qp[2*d4+1], kv.y);
            }
            float lo, hi; unpack2(sp, lo, hi);
            int kg = kt*64 + kk;
            s[j] = (kg < S_) ? (lo + hi) : -1e30f;
        }
        float mt = s[0];
#pragma unroll
        for (int j = 1; j < 8; j++) mt = fmaxf(mt, s[j]);
        mt = fmaxf(mt, __shfl_xor_sync(0xffffffffu, mt, 4, 8));
        mt = fmaxf(mt, __shfl_xor_sync(0xffffffffu, mt, 2, 8));
        mt = fmaxf(mt, __shfl_xor_sync(0xffffffffu, mt, 1, 8));
        float mn = fmaxf(m, mt);
        float r = __expf(m - mn);
        float p[8];
        float ls = 0.f;
#pragma unroll
        for (int j = 0; j < 8; j++) { p[j] = __expf(s[j] - mn); ls += p[j]; }
        ls += __shfl_xor_sync(0xffffffffu, ls, 4, 8);
        ls += __shfl_xor_sync(0xffffffffu, ls, 2, 8);
        ls += __shfl_xor_sync(0xffffffffu, ls, 1, 8);
        l = l * r + ls;
        m = mn;
#pragma unroll
        for (int j = 0; j < 8; j++) {
            int kk = lane8 + j*8;
            Ss[q*64 + (kk ^ qsw)] = p[j];
        }
        __syncwarp();
        ull rd = packdup(r);
#pragma unroll
        for (int e = 0; e < 4; e++) mul2(Op[e], rd);
#pragma unroll
        for (int kk = 0; kk < 64; kk++) {
            ull pv = packdup(Ss[q*64 + (kk ^ qsw)]);
            ulonglong2 v0 = *(const ulonglong2*)&Vs[kk*64 + lane8*8];
            ulonglong2 v1 = *(const ulonglong2*)&Vs[kk*64 + lane8*8 + 4];
            ffma2(Op[0], pv, v0.x);
            ffma2(Op[1], pv, v0.y);
            ffma2(Op[2], pv, v1.x);
            ffma2(Op[3], pv, v1.y);
        }
    }

    if (qg < S_) {
        float inv = 1.f / l;
        float O[8];
#pragma unroll
        for (int e = 0; e < 4; e++) unpack2(Op[e], O[2*e], O[2*e+1]);
        size_t rb = (size_t)(b * S_ + qg) * TRID_ + hh * HD_ + lane8*8;
#pragma unroll
        for (int e2 = 0; e2 < 4; e2++) {
            float x0 = O[2*e2] * inv, x1 = O[2*e2+1] * inv;
            __nv_bfloat16 h0, l0, h1, l1;
            split_bf(x0, h0, l0);
            split_bf(x1, h1, l1);
            __nv_bfloat162 hh2; hh2.x = h0; hh2.y = h1;
            __nv_bfloat162 ll2; ll2.x = l0; ll2.y = l1;
            *(__nv_bfloat162*)(ctx2 + rb + 2*e2)        = hh2;
            *(__nv_bfloat162*)(ctx2 + rb + D_ + 2*e2)   = hh2;
            *(__nv_bfloat162*)(ctx2 + rb + 2*D_ + 2*e2) = ll2;
        }
    }
}

// ===================== launch =====================
extern "C" void kernel_launch(void* const* d_in, const int* in_sizes, int n_in,
                              void* d_out, int out_size) {
    const float* x         = (const float*)d_in[0];
    const float* patch_w   = (const float*)d_in[1];
    const float* patch_b   = (const float*)d_in[2];
    const float* cls_token = (const float*)d_in[3];
    const float* pos_embed = (const float*)d_in[4];
    const float* ln1_g     = (const float*)d_in[5];
    const float* ln1_b     = (const float*)d_in[6];
    const float* qkv_w     = (const float*)d_in[7];
    const float* qkv_b     = (const float*)d_in[8];
    const float* out_w     = (const float*)d_in[9];
    const float* out_b     = (const float*)d_in[10];
    const float* ln2_g     = (const float*)d_in[11];
    const float* ln2_b     = (const float*)d_in[12];
    const float* fc1_w     = (const float*)d_in[13];
    const float* fc1_b     = (const float*)d_in[14];
    const float* fc2_w     = (const float*)d_in[15];
    const float* fc2_b     = (const float*)d_in[16];
    const float* lnf_g     = (const float*)d_in[17];
    const float* lnf_b     = (const float*)d_in[18];
    const float* head_w    = (const float*)d_in[19];
    float* out = (float*)d_out;

    float *h, *tok, *qkv, *cls;
    __nv_bfloat16 *x2, *ctx2, *hid2, *p2, *pw2, *qkvw2, *outw2, *fc1w2, *fc2w2;
    cudaGetSymbolAddress((void**)&h,     g_h);
    cudaGetSymbolAddress((void**)&tok,   g_tok);
    cudaGetSymbolAddress((void**)&qkv,   g_qkv);
    cudaGetSymbolAddress((void**)&cls,   g_cls);
    cudaGetSymbolAddress((void**)&x2,    g_x2);
    cudaGetSymbolAddress((void**)&ctx2,  g_ctx2);
    cudaGetSymbolAddress((void**)&hid2,  g_hid2);
    cudaGetSymbolAddress((void**)&p2,    g_p2);
    cudaGetSymbolAddress((void**)&pw2,   g_pw2);
    cudaGetSymbolAddress((void**)&qkvw2, g_qkvw2);
    cudaGetSymbolAddress((void**)&outw2, g_outw2);
    cudaGetSymbolAddress((void**)&fc1w2, g_fc1w2);
    cudaGetSymbolAddress((void**)&fc2w2, g_fc2w2);

    cudaFuncSetAttribute(gemm_mma<0>, cudaFuncAttributeMaxDynamicSharedMemorySize, GMM_SMEM);
    cudaFuncSetAttribute(gemm_mma<1>, cudaFuncAttributeMaxDynamicSharedMemorySize, GMM_SMEM);
    cudaFuncSetAttribute(gemm_mma<2>, cudaFuncAttributeMaxDynamicSharedMemorySize, GMM_SMEM);

    // ---- weight conversion ----
    {
        auto wlaunch = [](const float* src, __nv_bfloat16* dst, int R, int K) {
            size_t n = (size_t)R * K;
            wsplit_k<<<(unsigned)((n + 255) / 256), 256>>>(src, dst, R, K);
        };
        wlaunch(patch_w, pw2, D_, PD_);
        wlaunch(qkv_w, qkvw2, DEPTH_*TRID_, D_);
        wlaunch(out_w, outw2, DEPTH_*D_, D_);
        wlaunch(fc1_w, fc1w2, DEPTH_*HID_, D_);
        wlaunch(fc2_w, fc2w2, DEPTH_*D_, HID_);
    }

    // ---- patch embed ----
    patchify_k<<<(unsigned)(((size_t)BT_*PD_ + 255) / 256), 256>>>(x, p2);
    gemm_mma<0><<<dim3(D_/128, BT_/128), 256, GMM_SMEM>>>(p2, pw2, patch_b, nullptr,
                                                          tok, BT_, D_, 3*PD_);
    assemble_k<<<(T_*D_ + 255)/256, 256>>>(tok, cls_token, pos_embed, h);

    const int lnBlocks = (T_ + 7) / 8;
    for (int L = 0; L < DEPTH_; L++) {
        ln_k<1><<<lnBlocks, 256>>>(h, nullptr, x2, ln1_g + L*D_, ln1_b + L*D_, T_, D_);
        gemm_mma<0><<<dim3(TRID_/128, T_/128), 256, GMM_SMEM>>>(
            x2, qkvw2 + (size_t)L*TRID_*3*D_, qkv_b + L*TRID_, nullptr,
            qkv, T_, TRID_, 3*D_);
        attn_k<<<dim3(7, B_*HEADS_), 256>>>(qkv, ctx2);
        gemm_mma<1><<<dim3(D_/128, T_/128), 256, GMM_SMEM>>>(
            ctx2, outw2 + (size_t)L*D_*3*D_, out_b + L*D_, h,
            h, T_, D_, 3*D_);
        ln_k<1><<<lnBlocks, 256>>>(h, nullptr, x2, ln2_g + L*D_, ln2_b + L*D_, T_, D_);
        gemm_mma<2><<<dim3(HID_/128, T_/128), 256, GMM_SMEM>>>(
            x2, fc1w2 + (size_t)L*HID_*3*D_, fc1_b + L*HID_, nullptr,
            hid2, T_, HID_, 3*D_);
        gemm_mma<1><<<dim3(D_/128, T_/128), 256, GMM_SMEM>>>(
            hid2, fc2w2 + (size_t)L*D_*3*HID_, fc2_b + L*D_, h,
            h, T_, D_, 3*HID_);
    }

    ln_k<0><<<(B_ + 7)/8, 256>>>(h, cls, nullptr, lnf_g, lnf_b, B_, S_*D_);
    gemm32_k<<<dim3(1, 1), 256>>>(cls, head_w, out, B_, NCLS_, D_);
}